// round 8
// baseline (speedup 1.0000x reference)
#include <cuda_runtime.h>
#include <cstdint>
#include <cstddef>

#define B_   32
#define T_   512
#define KIN  1024
#define H_   1024
#define G_   4096
#define M_   (B_*T_)
#define JT   8
#define NBLK 128
#define NTHR 512            // 16 warps, 128 regs/thread

__device__ float g_xproj[(size_t)M_ * G_];
__device__ float g_h[2][B_*H_];
__device__ unsigned g_arr[8*32];   // tree barrier, 8 slots 128 B apart

typedef unsigned long long u64;

__device__ __forceinline__ void fma2(u64 &d, u64 a, u64 b){
    asm("fma.rn.f32x2 %0, %1, %2, %0;" : "+l"(d) : "l"(a), "l"(b));
}
__device__ __forceinline__ u64 pack2(float lo, float hi){
    u64 r; asm("mov.b64 %0, {%1,%2};" : "=l"(r) : "f"(lo), "f"(hi)); return r;
}
__device__ __forceinline__ float2 unpack2(u64 v){
    float2 f; asm("mov.b64 {%0,%1}, %2;" : "=f"(f.x), "=f"(f.y) : "l"(v)); return f;
}

// grid sync; 16 arrivals per slot per epoch
__device__ __forceinline__ void grid_sync(int jb, unsigned e)
{
    __syncthreads();
    if (threadIdx.x == 0) {
        __threadfence();
        atomicAdd(&g_arr[(jb & 7) * 32], 1u);
        unsigned tgt = 16u * e;
        volatile unsigned* a = g_arr;
        for (;;) {
            unsigned v0 = a[0*32], v1 = a[1*32], v2 = a[2*32], v3 = a[3*32];
            unsigned v4 = a[4*32], v5 = a[5*32], v6 = a[6*32], v7 = a[7*32];
            if (v0>=tgt && v1>=tgt && v2>=tgt && v3>=tgt &&
                v4>=tgt && v5>=tgt && v6>=tgt && v7>=tgt) break;
        }
        __threadfence();
    }
    __syncthreads();
}

// ---------------- scan smem layout (floats) ----------------
// hs rows: 1024 k + 8 pad floats per 32-float group -> pitch 1280.
#define HP2         1280
#define HS_FLOATS   (32*HP2)
#define PB_FLOATS   (16*16*32)               // [w][bl][c]
#define SP_FLOATS   (32*33)
#define SMEM_BYTES  ((HS_FLOATS + PB_FLOATS + SP_FLOATS)*4)

// xproj aliases: As2 u64[16][66], then Bst float[16][132]
#define XP_BST_OFF  (16*66*2)                // float offset

extern __shared__ float smemf[];

__global__ void __launch_bounds__(NTHR, 1) lstm_fused(
    const float* __restrict__ A,
    const float* __restrict__ h0,
    const float* __restrict__ c0,
    const float* __restrict__ Wih,
    const float* __restrict__ bih,
    const float* __restrict__ Whh,
    const float* __restrict__ bhh,
    float* __restrict__ out)
{
    const int tid = threadIdx.x;
    const int jb  = blockIdx.x;

    if (jb == 0 && tid < 8) { g_arr[tid*32] = 0u; __threadfence(); }
    unsigned epoch = 0;

    // ==============================================================
    // Phase A: xproj. 64m x 128n tiles, BK=16; 64 tiles per block.
    // ==============================================================
    {
        u64*   As2 = (u64*)smemf;                 // [16][66]
        float* Bst = smemf + XP_BST_OFF;          // [16][132]

        const int tx = tid & 31;
        const int ty = tid >> 5;
        const int wrow = tid >> 2;                // 0..127
        const int wk   = (tid & 3) * 4;
        const int lrow = (tid & 255) >> 2;        // 0..63
        const int lk   = (tid & 3) * 4;

        for (int i6 = 0; i6 < 64; i6++) {
            int tt = jb*64 + i6;
            int m0 = (tt >> 5) * 64;
            int n0 = (tt & 31) * 128;

            u64 acc[4][2];
            #pragma unroll
            for (int i = 0; i < 4; i++) { acc[i][0]=0ULL; acc[i][1]=0ULL; }

            const float* Arow = A   + (size_t)(m0 + lrow)*KIN + lk;
            const float* Wrow = Wih + (size_t)(n0 + wrow)*KIN + wk;

            for (int kc = 0; kc < KIN; kc += 16) {
                if (tid < 256) {
                    float4 av = *(const float4*)(Arow + kc);
                    As2[(lk+0)*66 + lrow] = pack2(av.x, av.x);
                    As2[(lk+1)*66 + lrow] = pack2(av.y, av.y);
                    As2[(lk+2)*66 + lrow] = pack2(av.z, av.z);
                    As2[(lk+3)*66 + lrow] = pack2(av.w, av.w);
                }
                float4 wv = *(const float4*)(Wrow + kc);
                Bst[(wk+0)*132 + wrow] = wv.x;
                Bst[(wk+1)*132 + wrow] = wv.y;
                Bst[(wk+2)*132 + wrow] = wv.z;
                Bst[(wk+3)*132 + wrow] = wv.w;
                __syncthreads();

                #pragma unroll
                for (int k = 0; k < 16; k++) {
                    const ulonglong2* ap =
                        (const ulonglong2*)&As2[k*66 + ty*4];
                    ulonglong2 a01 = ap[0];
                    ulonglong2 a23 = ap[1];
                    u64 b0 = *(const u64*)&Bst[k*132 + tx*4];
                    u64 b1 = *(const u64*)&Bst[k*132 + tx*4 + 2];
                    fma2(acc[0][0], a01.x, b0); fma2(acc[0][1], a01.x, b1);
                    fma2(acc[1][0], a01.y, b0); fma2(acc[1][1], a01.y, b1);
                    fma2(acc[2][0], a23.x, b0); fma2(acc[2][1], a23.x, b1);
                    fma2(acc[3][0], a23.y, b0); fma2(acc[3][1], a23.y, b1);
                }
                __syncthreads();
            }

            float bn0 = bih[n0 + tx*4];
            float bn1 = bih[n0 + tx*4 + 1];
            float bn2 = bih[n0 + tx*4 + 2];
            float bn3 = bih[n0 + tx*4 + 3];
            #pragma unroll
            for (int i = 0; i < 4; i++) {
                int m = m0 + ty*4 + i;
                float* crow = g_xproj + (size_t)m*G_ + n0 + tx*4;
                float2 v0 = unpack2(acc[i][0]);
                float2 v1 = unpack2(acc[i][1]);
                crow[0] = v0.x + bn0;
                crow[1] = v0.y + bn1;
                crow[2] = v1.x + bn2;
                crow[3] = v1.y + bn3;
            }
        }
    }

    grid_sync(jb, ++epoch);

    // ==============================================================
    // Phase B: scan. 16 warps; lane = (col-pair ll, k-group kg).
    // ==============================================================
    float* hs   = smemf;                    // [32][HP2]
    float* pbuf = smemf + HS_FLOATS;        // [16 w][16 bl][32 c]
    float* sp   = pbuf + PB_FLOATS;         // [32 c][33]

    const int w    = tid >> 5;
    const int lane = tid & 31;
    const int ll   = lane & 15;
    const int kg   = lane >> 4;
    const int cc0  = 2*ll;
    const int ks   = w*64 + kg*32;
    const int ksp  = w*80 + kg*40;          // padded offset

    const int n0c = (cc0>>3)*H_ + jb*JT + (cc0&7);
    const int n1c = ((cc0+1)>>3)*H_ + jb*JT + ((cc0+1)&7);

    u64 wA[16], wB[16];
    {
        const float4* pA = (const float4*)(Whh + (size_t)n0c*KIN + ks);
        const float4* pB = (const float4*)(Whh + (size_t)n1c*KIN + ks);
        #pragma unroll
        for (int m = 0; m < 8; m++) {
            float4 a = pA[m], b = pB[m];
            wA[2*m] = pack2(a.x, a.y); wA[2*m+1] = pack2(a.z, a.w);
            wB[2*m] = pack2(b.x, b.y); wB[2*m+1] = pack2(b.z, b.w);
        }
    }

    const bool upd = (tid < 256);
    const int ub = tid >> 3;
    const int uj = tid & 7;
    const int jg = jb*JT + uj;
    float cstate = 0.f;
    if (upd) cstate = c0[ub*H_ + jg];

    const size_t OFF_H = (size_t)B_*T_*H_;
    const size_t OFF_C = OFF_H + (size_t)B_*H_;

    for (int t = 0; t < T_; t++) {
        const float* hprev = (t == 0) ? h0 : g_h[t & 1];
        float*       hnext = g_h[(t + 1) & 1];

        // stage full h with k-group padding: 8192 float4, 16/thread
        {
            const float4* hsrc = (const float4*)hprev;
            #pragma unroll
            for (int it = 0; it < 16; it++) {
                int e = tid + NTHR*it;
                int r = e >> 8, c4 = e & 255;
                *(float4*)(hs + r*HP2 + c4*4 + (c4>>3)*8) =
                    hsrc[r*256 + c4];
            }
        }

        float xp0=0,xp1=0,xp2=0,xp3=0, bh0=0,bh1=0,bh2=0,bh3=0;
        if (upd) {
            const float* xrow = g_xproj + ((size_t)ub*T_ + t)*G_ + jg;
            xp0 = xrow[0]; xp1 = xrow[H_]; xp2 = xrow[2*H_]; xp3 = xrow[3*H_];
            bh0 = bhh[jg]; bh1 = bhh[H_+jg];
            bh2 = bhh[2*H_+jg]; bh3 = bhh[3*H_+jg];
        }
        __syncthreads();                     // hs ready

        #pragma unroll
        for (int X = 0; X < 2; X++) {
            if (X == 1 && tid < 128) {
                float p0 = sp[(0*8+uj)*33 + ub] + xp0 + bh0;
                float p1 = sp[(1*8+uj)*33 + ub] + xp1 + bh1;
                float p2 = sp[(2*8+uj)*33 + ub] + xp2 + bh2;
                float p3 = sp[(3*8+uj)*33 + ub] + xp3 + bh3;
                float ig = 1.f/(1.f+__expf(-p0));
                float fg = 1.f/(1.f+__expf(-p1));
                float og = 1.f/(1.f+__expf(-p2));
                float gg = tanhf(p3);
                float cn = cstate*fg + ig*gg;
                cstate = cn;
                float hn = og * tanhf(cn);
                hnext[ub*H_ + jg] = hn;
                out[((size_t)ub*T_ + t)*H_ + jg] = hn;
                if (t == T_-1) {
                    out[OFF_H + (size_t)ub*H_ + jg] = hn;
                    out[OFF_C + (size_t)ub*H_ + jg] = cn;
                }
            }

            #pragma unroll 2
            for (int bl = 0; bl < 16; bl++) {
                const ulonglong2* hb = (const ulonglong2*)
                    (hs + (X*16 + bl)*HP2 + ksp);
                u64 a0 = 0ULL, a1 = 0ULL;
                #pragma unroll
                for (int m = 0; m < 8; m++) {
                    ulonglong2 hv = hb[m];
                    fma2(a0, wA[2*m],   hv.x);
                    fma2(a1, wB[2*m],   hv.x);
                    fma2(a0, wA[2*m+1], hv.y);
                    fma2(a1, wB[2*m+1], hv.y);
                }
                float2 f0 = unpack2(a0), f1 = unpack2(a1);
                float p0 = f0.x + f0.y;
                float p1 = f1.x + f1.y;
                p0 += __shfl_xor_sync(0xffffffffu, p0, 16);
                p1 += __shfl_xor_sync(0xffffffffu, p1, 16);
                if (kg == 0) {
                    float2 st; st.x = p0; st.y = p1;
                    *(float2*)&pbuf[(w*16 + bl)*32 + cc0] = st;
                }
            }
            __syncthreads();                 // pbuf ready

            {
                int cc = tid & 31, bl = tid >> 5;
                float s = 0.f;
                #pragma unroll
                for (int ww = 0; ww < 16; ww++)
                    s += pbuf[(ww*16 + bl)*32 + cc];
                sp[cc*33 + X*16 + bl] = s;
            }
            __syncthreads();                 // sp[X] ready
        }

        if (tid >= 128 && tid < 256) {
            float p0 = sp[(0*8+uj)*33 + ub] + xp0 + bh0;
            float p1 = sp[(1*8+uj)*33 + ub] + xp1 + bh1;
            float p2 = sp[(2*8+uj)*33 + ub] + xp2 + bh2;
            float p3 = sp[(3*8+uj)*33 + ub] + xp3 + bh3;
            float ig = 1.f/(1.f+__expf(-p0));
            float fg = 1.f/(1.f+__expf(-p1));
            float og = 1.f/(1.f+__expf(-p2));
            float gg = tanhf(p3);
            float cn = cstate*fg + ig*gg;
            cstate = cn;
            float hn = og * tanhf(cn);
            hnext[ub*H_ + jg] = hn;
            out[((size_t)ub*T_ + t)*H_ + jg] = hn;
            if (t == T_-1) {
                out[OFF_H + (size_t)ub*H_ + jg] = hn;
                out[OFF_C + (size_t)ub*H_ + jg] = cn;
            }
        }

        if (t + 1 < T_) grid_sync(jb, ++epoch);
    }
}

extern "C" void kernel_launch(void* const* d_in, const int* in_sizes, int n_in,
                              void* d_out, int out_size)
{
    (void)in_sizes; (void)n_in; (void)out_size;
    const float* inputs = (const float*)d_in[0];
    const float* h0     = (const float*)d_in[1];
    const float* c0     = (const float*)d_in[2];
    const float* Wih    = (const float*)d_in[3];
    const float* bih    = (const float*)d_in[4];
    const float* Whh    = (const float*)d_in[5];
    const float* bhh    = (const float*)d_in[6];
    float* out = (float*)d_out;

    cudaFuncSetAttribute(lstm_fused,
                         cudaFuncAttributeMaxDynamicSharedMemorySize,
                         SMEM_BYTES);

    lstm_fused<<<NBLK, NTHR, SMEM_BYTES>>>(
        inputs, h0, c0, Wih, bih, Whh, bhh, out);
}

// round 9
// speedup vs baseline: 1.1160x; 1.1160x over previous
#include <cuda_runtime.h>
#include <cstdint>
#include <cstddef>

#define B_   32
#define T_   512
#define KIN  1024
#define H_   1024
#define G_   4096
#define M_   (B_*T_)
#define JT   8
#define NBLK 128
#define NTHR 1024            // 32 warps

__device__ float g_xproj[(size_t)M_ * G_];
__device__ float g_h[2][B_*H_];
__device__ unsigned g_arr[8*32];   // tree barrier, 8 slots 128 B apart

typedef unsigned long long u64;

__device__ __forceinline__ void fma2(u64 &d, u64 a, u64 b){
    asm("fma.rn.f32x2 %0, %1, %2, %0;" : "+l"(d) : "l"(a), "l"(b));
}
__device__ __forceinline__ u64 pack2(float lo, float hi){
    u64 r; asm("mov.b64 %0, {%1,%2};" : "=l"(r) : "f"(lo), "f"(hi)); return r;
}
__device__ __forceinline__ float2 unpack2(u64 v){
    float2 f; asm("mov.b64 {%0,%1}, %2;" : "=f"(f.x), "=f"(f.y) : "l"(v)); return f;
}

// grid sync; 16 arrivals per slot per epoch
__device__ __forceinline__ void grid_sync(int jb, unsigned e)
{
    __syncthreads();
    if (threadIdx.x == 0) {
        __threadfence();
        atomicAdd(&g_arr[(jb & 7) * 32], 1u);
        unsigned tgt = 16u * e;
        volatile unsigned* a = g_arr;
        for (;;) {
            unsigned v0 = a[0*32], v1 = a[1*32], v2 = a[2*32], v3 = a[3*32];
            unsigned v4 = a[4*32], v5 = a[5*32], v6 = a[6*32], v7 = a[7*32];
            if (v0>=tgt && v1>=tgt && v2>=tgt && v3>=tgt &&
                v4>=tgt && v5>=tgt && v6>=tgt && v7>=tgt) break;
        }
        __threadfence();
    }
    __syncthreads();
}

// ---------------- scan smem layout (floats) ----------------
#define HP          1024
#define HS_FLOATS   (32*HP)                  // 131 KB
#define PB_FLOATS   (32*16*32)               // [w][bl][c]  64 KB
#define SP_FLOATS   (32*33)
#define SMEM_BYTES  ((HS_FLOATS + PB_FLOATS + SP_FLOATS)*4)

// xproj aliases: As2 u64[16][258], then Bst float[16][132]
#define XP_AP       258
#define XP_BST_OFF  (16*XP_AP*2)             // float offset

extern __shared__ float smemf[];

__global__ void __launch_bounds__(NTHR, 1) lstm_fused(
    const float* __restrict__ A,
    const float* __restrict__ h0,
    const float* __restrict__ c0,
    const float* __restrict__ Wih,
    const float* __restrict__ bih,
    const float* __restrict__ Whh,
    const float* __restrict__ bhh,
    float* __restrict__ out)
{
    const int tid = threadIdx.x;
    const int jb  = blockIdx.x;

    if (jb == 0 && tid < 8) { g_arr[tid*32] = 0u; __threadfence(); }
    unsigned epoch = 0;

    // ==============================================================
    // Phase A: xproj. 256m x 128n tiles, 16 per block (round-7 ver.)
    // ==============================================================
    {
        u64*   As2 = (u64*)smemf;            // [16][XP_AP]
        float* Bst = smemf + XP_BST_OFF;     // [16][132]

        const int tx   = tid & 31;           // n quad
        const int ty   = tid >> 5;           // m oct
        const int arow = tid >> 2;           // 0..255
        const int akq  = (tid & 3) * 4;

        for (int i6 = 0; i6 < 16; i6++) {
            int tt = jb*16 + i6;
            int m0 = (tt >> 5) * 256;
            int n0 = (tt & 31) * 128;

            u64 acc[8][2];
            #pragma unroll
            for (int i = 0; i < 8; i++) { acc[i][0]=0ULL; acc[i][1]=0ULL; }

            const float* Ap = A + (size_t)(m0 + arow)*KIN + akq;
            const float* Wp = Wih + (size_t)(n0 + (arow & 127))*KIN + akq;

            for (int kc = 0; kc < KIN; kc += 16) {
                float4 av = *(const float4*)(Ap + kc);
                float4 wv;
                if (tid < 512) wv = *(const float4*)(Wp + kc);

                As2[(akq+0)*XP_AP + arow] = pack2(av.x, av.x);
                As2[(akq+1)*XP_AP + arow] = pack2(av.y, av.y);
                As2[(akq+2)*XP_AP + arow] = pack2(av.z, av.z);
                As2[(akq+3)*XP_AP + arow] = pack2(av.w, av.w);
                if (tid < 512) {
                    Bst[(akq+0)*132 + arow] = wv.x;
                    Bst[(akq+1)*132 + arow] = wv.y;
                    Bst[(akq+2)*132 + arow] = wv.z;
                    Bst[(akq+3)*132 + arow] = wv.w;
                }
                __syncthreads();

                #pragma unroll
                for (int k = 0; k < 16; k++) {
                    const ulonglong2* ap =
                        (const ulonglong2*)&As2[k*XP_AP + ty*8];
                    ulonglong2 bv =
                        *(const ulonglong2*)&Bst[k*132 + tx*4];
                    #pragma unroll
                    for (int mh = 0; mh < 4; mh++) {
                        ulonglong2 a2 = ap[mh];
                        fma2(acc[2*mh  ][0], a2.x, bv.x);
                        fma2(acc[2*mh  ][1], a2.x, bv.y);
                        fma2(acc[2*mh+1][0], a2.y, bv.x);
                        fma2(acc[2*mh+1][1], a2.y, bv.y);
                    }
                }
                __syncthreads();
            }

            float4 bn = *(const float4*)(bih + n0 + tx*4);
            #pragma unroll
            for (int i = 0; i < 8; i++) {
                float2 v0 = unpack2(acc[i][0]);
                float2 v1 = unpack2(acc[i][1]);
                float4 o;
                o.x = v0.x + bn.x; o.y = v0.y + bn.y;
                o.z = v1.x + bn.z; o.w = v1.y + bn.w;
                *(float4*)(g_xproj + (size_t)(m0 + ty*8 + i)*G_
                           + n0 + tx*4) = o;
            }
        }
    }

    grid_sync(jb, ++epoch);

    // ==============================================================
    // Phase B: scan. 32 warps; lane = (col-pair ll, k-group kg).
    // Thread: 2 cols x 16 k -> wA[8]+wB[8] = 32 regs.
    // 2 distinct LDS addrs/warp (64 B apart); kg joined by shfl.
    // Step pipeline: stage1 under main0; update0 under main1.
    // ==============================================================
    float* hs   = smemf;                    // [32][HP]
    float* pbuf = smemf + HS_FLOATS;        // [32 w][16 bl][32 c]
    float* sp   = pbuf + PB_FLOATS;         // [32 c][33]

    const int w    = tid >> 5;              // 0..31
    const int lane = tid & 31;
    const int ll   = lane & 15;
    const int kg   = lane >> 4;
    const int cc0  = 2*ll;
    const int ks   = w*32 + kg*16;          // k base

    const int n0c = (cc0>>3)*H_ + jb*JT + (cc0&7);
    const int n1c = ((cc0+1)>>3)*H_ + jb*JT + ((cc0+1)&7);

    u64 wA[8], wB[8];
    {
        const float4* pA = (const float4*)(Whh + (size_t)n0c*KIN + ks);
        const float4* pB = (const float4*)(Whh + (size_t)n1c*KIN + ks);
        #pragma unroll
        for (int m = 0; m < 4; m++) {
            float4 a = pA[m], b = pB[m];
            wA[2*m] = pack2(a.x, a.y); wA[2*m+1] = pack2(a.z, a.w);
            wB[2*m] = pack2(b.x, b.y); wB[2*m+1] = pack2(b.z, b.w);
        }
    }

    const bool upd = (tid < 256);
    const int ub = tid >> 3;                // 0..31 (tid<256)
    const int uj = tid & 7;
    const int jg = jb*JT + uj;
    float cstate = 0.f;
    if (upd) cstate = c0[ub*H_ + jg];

    const size_t OFF_H = (size_t)B_*T_*H_;
    const size_t OFF_C = OFF_H + (size_t)B_*H_;

    for (int t = 0; t < T_; t++) {
        const float* hprev = (t == 0) ? h0 : g_h[t & 1];
        float*       hnext = g_h[(t + 1) & 1];
        const float4* hsrc = (const float4*)hprev;

        // prefetch xproj + bhh
        float xp0=0,xp1=0,xp2=0,xp3=0, bh0=0,bh1=0,bh2=0,bh3=0;
        if (upd) {
            const float* xrow = g_xproj + ((size_t)ub*T_ + t)*G_ + jg;
            xp0 = xrow[0]; xp1 = xrow[H_]; xp2 = xrow[2*H_]; xp3 = xrow[3*H_];
            bh0 = bhh[jg]; bh1 = bhh[H_+jg];
            bh2 = bhh[2*H_+jg]; bh3 = bhh[3*H_+jg];
        }

        // stage half 0 (b rows 0..15): 4096 float4
        #pragma unroll
        for (int it = 0; it < 4; it++) {
            int e = tid + NTHR*it;
            int r = e >> 8, c4 = e & 255;
            *(float4*)(hs + r*HP + c4*4) = hsrc[r*256 + c4];
        }
        __syncthreads();                     // hs half0 ready

        // stage half 1 (hidden under main0)
        #pragma unroll
        for (int it = 0; it < 4; it++) {
            int e = tid + NTHR*it;
            int r = (e >> 8) + 16, c4 = e & 255;
            *(float4*)(hs + r*HP + c4*4) = hsrc[r*256 + c4];
        }

        // main0: b rows 0..15
        #pragma unroll 4
        for (int bl = 0; bl < 16; bl++) {
            const ulonglong2* hb =
                (const ulonglong2*)(hs + bl*HP + ks);
            u64 a0 = 0ULL, a1 = 0ULL;
            #pragma unroll
            for (int m = 0; m < 4; m++) {
                ulonglong2 hv = hb[m];
                fma2(a0, wA[2*m],   hv.x); fma2(a0, wA[2*m+1], hv.y);
                fma2(a1, wB[2*m],   hv.x); fma2(a1, wB[2*m+1], hv.y);
            }
            float2 f0 = unpack2(a0), f1 = unpack2(a1);
            float p0 = f0.x + f0.y;
            float p1 = f1.x + f1.y;
            p0 += __shfl_xor_sync(0xffffffffu, p0, 16);
            p1 += __shfl_xor_sync(0xffffffffu, p1, 16);
            if (kg == 0) {
                float2 st; st.x = p0; st.y = p1;
                *(float2*)&pbuf[(w*16 + bl)*32 + cc0] = st;
            }
        }
        __syncthreads();                     // pbuf0 + hs half1 ready

        // reduce0
        if (tid < 512) {
            int cc = tid & 31, bl = tid >> 5;
            float s = 0.f;
            #pragma unroll
            for (int ww = 0; ww < 32; ww++)
                s += pbuf[(ww*16 + bl)*32 + cc];
            sp[cc*33 + bl] = s;
        }
        __syncthreads();                     // sp half0 ready

        // update half0 (tid<128) overlapped with main1
        if (tid < 128) {
            float p0 = sp[(0*8+uj)*33 + ub] + xp0 + bh0;
            float p1 = sp[(1*8+uj)*33 + ub] + xp1 + bh1;
            float p2 = sp[(2*8+uj)*33 + ub] + xp2 + bh2;
            float p3 = sp[(3*8+uj)*33 + ub] + xp3 + bh3;
            float ig = 1.f/(1.f+__expf(-p0));
            float fg = 1.f/(1.f+__expf(-p1));
            float og = 1.f/(1.f+__expf(-p2));
            float gg = tanhf(p3);
            float cn = cstate*fg + ig*gg;
            cstate = cn;
            float hn = og * tanhf(cn);
            hnext[ub*H_ + jg] = hn;
            out[((size_t)ub*T_ + t)*H_ + jg] = hn;
            if (t == T_-1) {
                out[OFF_H + (size_t)ub*H_ + jg] = hn;
                out[OFF_C + (size_t)ub*H_ + jg] = cn;
            }
        }

        // main1: b rows 16..31
        #pragma unroll 4
        for (int bl = 0; bl < 16; bl++) {
            const ulonglong2* hb =
                (const ulonglong2*)(hs + (16 + bl)*HP + ks);
            u64 a0 = 0ULL, a1 = 0ULL;
            #pragma unroll
            for (int m = 0; m < 4; m++) {
                ulonglong2 hv = hb[m];
                fma2(a0, wA[2*m],   hv.x); fma2(a0, wA[2*m+1], hv.y);
                fma2(a1, wB[2*m],   hv.x); fma2(a1, wB[2*m+1], hv.y);
            }
            float2 f0 = unpack2(a0), f1 = unpack2(a1);
            float p0 = f0.x + f0.y;
            float p1 = f1.x + f1.y;
            p0 += __shfl_xor_sync(0xffffffffu, p0, 16);
            p1 += __shfl_xor_sync(0xffffffffu, p1, 16);
            if (kg == 0) {
                float2 st; st.x = p0; st.y = p1;
                *(float2*)&pbuf[(w*16 + bl)*32 + cc0] = st;
            }
        }
        __syncthreads();                     // pbuf1 ready

        // reduce1
        if (tid < 512) {
            int cc = tid & 31, bl = tid >> 5;
            float s = 0.f;
            #pragma unroll
            for (int ww = 0; ww < 32; ww++)
                s += pbuf[(ww*16 + bl)*32 + cc];
            sp[cc*33 + 16 + bl] = s;
        }
        __syncthreads();                     // sp half1 ready

        // update half1 (tid 128..255, ub 16..31)
        if (tid >= 128 && tid < 256) {
            float p0 = sp[(0*8+uj)*33 + ub] + xp0 + bh0;
            float p1 = sp[(1*8+uj)*33 + ub] + xp1 + bh1;
            float p2 = sp[(2*8+uj)*33 + ub] + xp2 + bh2;
            float p3 = sp[(3*8+uj)*33 + ub] + xp3 + bh3;
            float ig = 1.f/(1.f+__expf(-p0));
            float fg = 1.f/(1.f+__expf(-p1));
            float og = 1.f/(1.f+__expf(-p2));
            float gg = tanhf(p3);
            float cn = cstate*fg + ig*gg;
            cstate = cn;
            float hn = og * tanhf(cn);
            hnext[ub*H_ + jg] = hn;
            out[((size_t)ub*T_ + t)*H_ + jg] = hn;
            if (t == T_-1) {
                out[OFF_H + (size_t)ub*H_ + jg] = hn;
                out[OFF_C + (size_t)ub*H_ + jg] = cn;
            }
        }

        if (t + 1 < T_) grid_sync(jb, ++epoch);
    }
}

extern "C" void kernel_launch(void* const* d_in, const int* in_sizes, int n_in,
                              void* d_out, int out_size)
{
    (void)in_sizes; (void)n_in; (void)out_size;
    const float* inputs = (const float*)d_in[0];
    const float* h0     = (const float*)d_in[1];
    const float* c0     = (const float*)d_in[2];
    const float* Wih    = (const float*)d_in[3];
    const float* bih    = (const float*)d_in[4];
    const float* Whh    = (const float*)d_in[5];
    const float* bhh    = (const float*)d_in[6];
    float* out = (float*)d_out;

    cudaFuncSetAttribute(lstm_fused,
                         cudaFuncAttributeMaxDynamicSharedMemorySize,
                         SMEM_BYTES);

    lstm_fused<<<NBLK, NTHR, SMEM_BYTES>>>(
        inputs, h0, c0, Wih, bih, Whh, bhh, out);
}